// round 5
// baseline (speedup 1.0000x reference)
#include <cuda_runtime.h>

// ---------------------------------------------------------------------------
// LNSNet: conv1(1->32,3x3)+relu+pool2 -> conv2(32->64,3x3)+relu+pool2
//         -> fc1(9216->128)+relu -> fc2(128->10)
// Batch 512. All fp32.
// ---------------------------------------------------------------------------

// Scratch (device globals: allocation-free rule)
__device__ float g_p1[512 * 32 * 26 * 26];     // pool1 output, 44.3 MB
__device__ float g_p2[512 * 64 * 12 * 12];     // pool2 output (== flattened fc1 input)
__device__ float g_part[16 * 512 * 128];       // fc1 split-K partials
__device__ float g_h[512 * 128];               // fc1 relu output

// ---------------------------------------------------------------------------
// Kernel 1: conv1 (1 ch in, 32 out, 3x3, valid) + ReLU + 2x2 maxpool
// One block per batch image. Input plane cached in smem (pitch 55).
// ---------------------------------------------------------------------------
__global__ void __launch_bounds__(256) k_conv1(const float* __restrict__ x,
                                               const float* __restrict__ w,
                                               const float* __restrict__ bias)
{
    __shared__ float s_x[54 * 55];
    __shared__ float s_w[32 * 9];
    __shared__ float s_b[32];

    const int bb = blockIdx.x;
    const float* xb = x + bb * 54 * 54;
    for (int i = threadIdx.x; i < 54 * 54; i += 256) {
        int y = i / 54, c = i - y * 54;
        s_x[y * 55 + c] = xb[i];
    }
    for (int i = threadIdx.x; i < 32 * 9; i += 256) s_w[i] = w[i];
    if (threadIdx.x < 32) s_b[threadIdx.x] = bias[threadIdx.x];
    __syncthreads();

    float* outb = g_p1 + bb * 32 * 676;
    for (int oc = 0; oc < 32; oc++) {
        float wr[9];
#pragma unroll
        for (int i = 0; i < 9; i++) wr[i] = s_w[oc * 9 + i];
        const float bv = s_b[oc];
        for (int pos = threadIdx.x; pos < 676; pos += 256) {
            const int py = pos / 26, px = pos - py * 26;
            const int Y0 = py * 2, X0 = px * 2;
            float in[4][4];
#pragma unroll
            for (int dy = 0; dy < 4; dy++)
#pragma unroll
                for (int dx = 0; dx < 4; dx++)
                    in[dy][dx] = s_x[(Y0 + dy) * 55 + X0 + dx];
            float m = 0.0f;  // relu floor; max(relu(c)) == relu(max(c))
#pragma unroll
            for (int dy = 0; dy < 2; dy++)
#pragma unroll
                for (int dx = 0; dx < 2; dx++) {
                    float acc = bv;
#pragma unroll
                    for (int ky = 0; ky < 3; ky++)
#pragma unroll
                        for (int kx = 0; kx < 3; kx++)
                            acc = fmaf(wr[ky * 3 + kx], in[dy + ky][dx + kx], acc);
                    m = fmaxf(m, acc);
                }
            outb[oc * 676 + pos] = m;
        }
    }
}

// ---------------------------------------------------------------------------
// Kernel 2: conv2 (32->64, 3x3, valid) + ReLU + 2x2 maxpool.  THE hot kernel.
// One block per batch image (512 blocks, 576 threads, 1 CTA/SM).
// smem: full input 32x26x26 (pitch 27) + all weights 64x288  (~160 KB dyn).
// Each thread: 8 oc x (2y x 4x conv positions) register tile = 64 accumulators.
// Per k-step: 8 input LDS + 8 weight LDS (broadcast) : 64 FMA  -> FFMA-bound.
// ---------------------------------------------------------------------------
#define C2_IN_FLOATS (32 * 26 * 27)   // 22464
#define C2_W_FLOATS  (64 * 288)       // 18432
#define C2_SMEM_BYTES ((C2_IN_FLOATS + C2_W_FLOATS) * 4)

__global__ void __launch_bounds__(576, 1) k_conv2(const float* __restrict__ w,
                                                  const float* __restrict__ bias)
{
    extern __shared__ float sm[];
    float* s_in = sm;                 // [32][26][27]
    float* s_w  = sm + C2_IN_FLOATS;  // [64][288]
    __shared__ float s_b[64];

    const int bb = blockIdx.x;
    const float* inb = g_p1 + bb * 32 * 676;
    for (int i = threadIdx.x; i < 32 * 676; i += 576) {
        int ic = i / 676, r = i - ic * 676;
        int y = r / 26, xx = r - y * 26;
        s_in[ic * 702 + y * 27 + xx] = inb[i];
    }
    for (int i = threadIdx.x; i < 64 * 288; i += 576) s_w[i] = w[i];
    if (threadIdx.x < 64) s_b[threadIdx.x] = bias[threadIdx.x];
    __syncthreads();

    const int t = threadIdx.x;
    const int ocg = t / 72;           // 0..7  -> oc block of 8
    const int pr  = t - ocg * 72;     // 0..71
    const int py  = pr / 6;           // pool row 0..11
    const int pxp = pr - py * 6;      // pool col pair 0..5
    const int Y0 = py * 2, X0 = pxp * 4;

    float acc[8][8];
#pragma unroll
    for (int j = 0; j < 8; j++)
#pragma unroll
        for (int p = 0; p < 8; p++) acc[j][p] = 0.0f;

    const float* wp = s_w + ocg * 8 * 288;
    for (int ic = 0; ic < 32; ic++) {
        const float* ip = s_in + ic * 702 + Y0 * 27 + X0;
#pragma unroll
        for (int ky = 0; ky < 3; ky++) {
#pragma unroll
            for (int kx = 0; kx < 3; kx++) {
                float iv[8];
#pragma unroll
                for (int dy = 0; dy < 2; dy++)
#pragma unroll
                    for (int dx = 0; dx < 4; dx++)
                        iv[dy * 4 + dx] = ip[(ky + dy) * 27 + kx + dx];
                const int widx = ic * 9 + ky * 3 + kx;
#pragma unroll
                for (int j = 0; j < 8; j++) {
                    const float wv = wp[j * 288 + widx];
#pragma unroll
                    for (int p = 0; p < 8; p++)
                        acc[j][p] = fmaf(wv, iv[p], acc[j][p]);
                }
            }
        }
    }

    // Epilogue: +bias, relu, 2x2 maxpool over the 2x4 conv positions.
    float* outb = g_p2 + bb * 64 * 144;
#pragma unroll
    for (int j = 0; j < 8; j++) {
        const int oc = ocg * 8 + j;
        const float bv = s_b[oc];
#pragma unroll
        for (int c = 0; c < 2; c++) {
            float m = 0.0f;
#pragma unroll
            for (int dy = 0; dy < 2; dy++)
#pragma unroll
                for (int dx = 0; dx < 2; dx++)
                    m = fmaxf(m, acc[j][dy * 4 + c * 2 + dx] + bv);
            outb[oc * 144 + py * 12 + (pxp * 2 + c)] = m;
        }
    }
}

// ---------------------------------------------------------------------------
// Kernel 3: fc1 GEMM, split-K.  C[b][n] = sum_k A[b][k] * W[n][k]
// A = g_p2 [512][9216], W = fc1_w [128][9216].
// Grid (8 m-tiles, 16 k-splits of 576). Block tile 64m x 128n, thread 4x8.
// Each block writes its own disjoint partial slice -> deterministic.
// ---------------------------------------------------------------------------
__global__ void __launch_bounds__(256) k_fc1(const float* __restrict__ W)
{
    __shared__ float As[64][17];
    __shared__ float Bs[128][17];

    const int mb = blockIdx.x;     // 0..7
    const int sp = blockIdx.y;     // 0..15
    const int tid = threadIdx.x;
    const float* Ab = g_p2 + (mb * 64) * 9216;
    const int k0 = sp * 576;

    float acc[4][8];
#pragma unroll
    for (int i = 0; i < 4; i++)
#pragma unroll
        for (int j = 0; j < 8; j++) acc[i][j] = 0.0f;

    const int tm = tid >> 4, tn = tid & 15;
    const int lr = tid >> 2;            // 0..63
    const int lc = (tid & 3) * 4;       // 0,4,8,12

    for (int ks = 0; ks < 576; ks += 16) {
        {
            const float4 v = *(const float4*)(Ab + lr * 9216 + k0 + ks + lc);
            As[lr][lc + 0] = v.x; As[lr][lc + 1] = v.y;
            As[lr][lc + 2] = v.z; As[lr][lc + 3] = v.w;
#pragma unroll
            for (int g = 0; g < 2; g++) {
                const int rr = lr + 64 * g;
                const float4 u = *(const float4*)(W + rr * 9216 + k0 + ks + lc);
                Bs[rr][lc + 0] = u.x; Bs[rr][lc + 1] = u.y;
                Bs[rr][lc + 2] = u.z; Bs[rr][lc + 3] = u.w;
            }
        }
        __syncthreads();
#pragma unroll
        for (int kk = 0; kk < 16; kk++) {
            float a[4], bv[8];
#pragma unroll
            for (int i = 0; i < 4; i++) a[i] = As[tm * 4 + i][kk];
#pragma unroll
            for (int j = 0; j < 8; j++) bv[j] = Bs[tn * 8 + j][kk];
#pragma unroll
            for (int i = 0; i < 4; i++)
#pragma unroll
                for (int j = 0; j < 8; j++)
                    acc[i][j] = fmaf(a[i], bv[j], acc[i][j]);
        }
        __syncthreads();
    }

    float* out = g_part + sp * (512 * 128) + (mb * 64) * 128;
#pragma unroll
    for (int i = 0; i < 4; i++)
#pragma unroll
        for (int j = 0; j < 8; j++)
            out[(tm * 4 + i) * 128 + tn * 8 + j] = acc[i][j];
}

// ---------------------------------------------------------------------------
// Kernel 4: reduce split-K partials + bias + ReLU
// ---------------------------------------------------------------------------
__global__ void k_fc1red(const float* __restrict__ b1)
{
    const int idx = blockIdx.x * blockDim.x + threadIdx.x;   // 65536
    const int n = idx & 127;
    float s = b1[n];
#pragma unroll
    for (int sp = 0; sp < 16; sp++) s += g_part[sp * 65536 + idx];
    g_h[idx] = fmaxf(s, 0.0f);
}

// ---------------------------------------------------------------------------
// Kernel 5: fc2 (128 -> 10). One block per batch row.
// ---------------------------------------------------------------------------
__global__ void __launch_bounds__(128) k_fc2(const float* __restrict__ W2,
                                             const float* __restrict__ b2,
                                             float* __restrict__ out)
{
    __shared__ float sh[128];
    const int bb = blockIdx.x;
    const int tid = threadIdx.x;
    sh[tid] = g_h[bb * 128 + tid];
    __syncthreads();
    const int warp = tid >> 5, lane = tid & 31;
    for (int o = warp; o < 10; o += 4) {
        float s = 0.0f;
#pragma unroll
        for (int i = 0; i < 4; i++)
            s = fmaf(sh[lane + 32 * i], W2[o * 128 + lane + 32 * i], s);
#pragma unroll
        for (int off = 16; off > 0; off >>= 1)
            s += __shfl_down_sync(0xffffffffu, s, off);
        if (lane == 0) out[bb * 10 + o] = s + b2[o];
    }
}

// ---------------------------------------------------------------------------
extern "C" void kernel_launch(void* const* d_in, const int* in_sizes, int n_in,
                              void* d_out, int out_size)
{
    const float* x   = (const float*)d_in[0];
    const float* c1w = (const float*)d_in[1];
    const float* c1b = (const float*)d_in[2];
    const float* c2w = (const float*)d_in[3];
    const float* c2b = (const float*)d_in[4];
    const float* f1w = (const float*)d_in[5];
    const float* f1b = (const float*)d_in[6];
    const float* f2w = (const float*)d_in[7];
    const float* f2b = (const float*)d_in[8];
    float* out = (float*)d_out;

    cudaFuncSetAttribute(k_conv2, cudaFuncAttributeMaxDynamicSharedMemorySize,
                         C2_SMEM_BYTES);

    k_conv1<<<512, 256>>>(x, c1w, c1b);
    k_conv2<<<512, 576, C2_SMEM_BYTES>>>(c2w, c2b);
    dim3 g3(8, 16);
    k_fc1<<<g3, 256>>>(f1w);
    k_fc1red<<<256, 256>>>(f1b);
    k_fc2<<<512, 128>>>(f2w, f2b, out);
}

// round 9
// speedup vs baseline: 1.5744x; 1.5744x over previous
#include <cuda_runtime.h>
#include <cstdint>

// ---------------------------------------------------------------------------
// LNSNet: conv1(1->32,3x3)+relu+pool2 -> conv2(32->64,3x3)+relu+pool2 (mma.sync tf32)
//         -> fc1(9216->128)+relu -> fc2(128->10).  Batch 512.
// ---------------------------------------------------------------------------

__device__ float g_p1[512 * 32 * 26 * 26];     // pool1 output
__device__ float g_p2[512 * 64 * 12 * 12];     // pool2 output (fc1 input)
__device__ float g_part[16 * 512 * 128];       // fc1 split-K partials
__device__ float g_h[512 * 128];               // fc1 relu output

__device__ __forceinline__ float tf32_rna(float v) {
    uint32_t u;
    asm("cvt.rna.tf32.f32 %0, %1;" : "=r"(u) : "f"(v));
    return __uint_as_float(u);
}

// m16n8k8 tf32 mma, row.col, fp32 accumulate (sm_80+ baseline PTX)
__device__ __forceinline__ void mma_tf32(float* c,
                                         float a0, float a1, float a2, float a3,
                                         float b0, float b1)
{
    asm volatile(
        "mma.sync.aligned.m16n8k8.row.col.f32.tf32.tf32.f32 "
        "{%0,%1,%2,%3}, {%4,%5,%6,%7}, {%8,%9}, {%0,%1,%2,%3};"
        : "+f"(c[0]), "+f"(c[1]), "+f"(c[2]), "+f"(c[3])
        : "r"(__float_as_uint(a0)), "r"(__float_as_uint(a1)),
          "r"(__float_as_uint(a2)), "r"(__float_as_uint(a3)),
          "r"(__float_as_uint(b0)), "r"(__float_as_uint(b1)));
}

// ---------------------------------------------------------------------------
// Kernel 1: conv1 + ReLU + maxpool (fp32)
// ---------------------------------------------------------------------------
__global__ void __launch_bounds__(256) k_conv1(const float* __restrict__ x,
                                               const float* __restrict__ w,
                                               const float* __restrict__ bias)
{
    __shared__ float s_x[54 * 55];
    __shared__ float s_w[32 * 9];
    __shared__ float s_b[32];

    const int bb = blockIdx.x;
    const float* xb = x + bb * 54 * 54;
    for (int i = threadIdx.x; i < 54 * 54; i += 256) {
        int y = i / 54, c = i - y * 54;
        s_x[y * 55 + c] = xb[i];
    }
    for (int i = threadIdx.x; i < 32 * 9; i += 256) s_w[i] = w[i];
    if (threadIdx.x < 32) s_b[threadIdx.x] = bias[threadIdx.x];
    __syncthreads();

    float* outb = g_p1 + bb * 32 * 676;
    for (int oc = 0; oc < 32; oc++) {
        float wr[9];
#pragma unroll
        for (int i = 0; i < 9; i++) wr[i] = s_w[oc * 9 + i];
        const float bv = s_b[oc];
        for (int pos = threadIdx.x; pos < 676; pos += 256) {
            const int py = pos / 26, px = pos - py * 26;
            const int Y0 = py * 2, X0 = px * 2;
            float in[4][4];
#pragma unroll
            for (int dy = 0; dy < 4; dy++)
#pragma unroll
                for (int dx = 0; dx < 4; dx++)
                    in[dy][dx] = s_x[(Y0 + dy) * 55 + X0 + dx];
            float m = 0.0f;
#pragma unroll
            for (int dy = 0; dy < 2; dy++)
#pragma unroll
                for (int dx = 0; dx < 2; dx++) {
                    float acc = bv;
#pragma unroll
                    for (int ky = 0; ky < 3; ky++)
#pragma unroll
                        for (int kx = 0; kx < 3; kx++)
                            acc = fmaf(wr[ky * 3 + kx], in[dy + ky][dx + kx], acc);
                    m = fmaxf(m, acc);
                }
            outb[oc * 676 + pos] = m;
        }
    }
}

// ---------------------------------------------------------------------------
// Kernel 2: conv2 via mma.sync tf32 implicit-im2col + ReLU + maxpool.
// One CTA per image, 288 threads (9 warps).
// D[576 pos x 64 oc] = A[576 x 288] * B[288 x 64].
// Warp w owns m-tiles {4w..4w+3} (16 rows each) x all 8 n-tiles.
// A fragments gathered directly from X planes via offset table (no im2col buf).
// B staged as [k][72] (stride-72 pad -> conflict-free fragment loads).
// Dyn smem (floats): Xs[21632] | Bs[288*72=20736] | offs[288 ints]
//   epilogue reuses Xs/Bs region as conv buffer [576][66].
// ---------------------------------------------------------------------------
#define C2_XS     21632
#define C2_BS     20736
#define C2_SMEMF  (C2_XS + C2_BS + 288)          // 42656 floats
#define C2_DSMEM  (C2_SMEMF * 4)                 // 170624 bytes

__global__ void __launch_bounds__(288, 1) k_conv2(const float* __restrict__ w,
                                                  const float* __restrict__ bias)
{
    extern __shared__ float sm[];
    float* Xs  = sm;                 // 32 planes of 26x26
    float* Bsm = sm + C2_XS;         // [288][72]
    int*   offs = (int*)(sm + C2_XS + C2_BS);    // [288]
    __shared__ float s_b[64];

    const int tid = threadIdx.x;
    const int wid = tid >> 5, lane = tid & 31;
    const int grp = lane >> 2, qid = lane & 3;
    const int bb = blockIdx.x;

    // ---- prologue: offset table, bias, B (warps 0-1), X (warps 2-8) ----
    if (tid < 288) {
        const int ic = tid / 9, r = tid - ic * 9;
        offs[tid] = ic * 676 + (r / 3) * 26 + (r % 3);
    }
    if (tid < 64) s_b[tid] = bias[tid];

    if (wid < 2) {
        // B: each thread owns one oc row, streams k. STS conflict-free
        // (same k across warp, oc=lane spans 32 banks).
        const int oc = wid * 32 + lane;
        const float* wr = w + oc * 288;
#pragma unroll 4
        for (int k = 0; k < 288; k += 4) {
            const float4 v = *(const float4*)(wr + k);
            Bsm[(k + 0) * 72 + oc] = tf32_rna(v.x);
            Bsm[(k + 1) * 72 + oc] = tf32_rna(v.y);
            Bsm[(k + 2) * 72 + oc] = tf32_rna(v.z);
            Bsm[(k + 3) * 72 + oc] = tf32_rna(v.w);
        }
    } else {
        const float* src = g_p1 + bb * C2_XS;
        for (int i = tid - 64; i < C2_XS; i += 224)
            Xs[i] = tf32_rna(src[i]);
    }
    __syncthreads();

    // per-thread A-row position offsets for the 4 m-tiles
    int poA[4], poB[4];
#pragma unroll
    for (int mt = 0; mt < 4; mt++) {
        const int rA = (wid * 4 + mt) * 16 + grp;
        const int yA = rA / 24, xA = rA - yA * 24;
        poA[mt] = yA * 26 + xA;
        const int rB = rA + 8;
        const int yB = rB / 24, xB = rB - yB * 24;
        poB[mt] = yB * 26 + xB;
    }

    float c[4][8][4];
#pragma unroll
    for (int mt = 0; mt < 4; mt++)
#pragma unroll
        for (int nt = 0; nt < 8; nt++)
#pragma unroll
            for (int j = 0; j < 4; j++) c[mt][nt][j] = 0.0f;

    // ---- mainloop: 36 k-steps of 8 ----
    for (int ks = 0; ks < 36; ks++) {
        const int klo = ks * 8 + qid;
        const int offlo = offs[klo];
        const int offhi = offs[klo + 4];

        // B fragments: row = klo (b0), klo+4 (b1); col = nt*8 + grp
        const float* bl = Bsm + klo * 72 + grp;
        float bq[8][2];
#pragma unroll
        for (int nt = 0; nt < 8; nt++) {
            bq[nt][0] = bl[nt * 8];
            bq[nt][1] = bl[4 * 72 + nt * 8];
        }

#pragma unroll
        for (int mt = 0; mt < 4; mt++) {
            const float a0 = Xs[offlo + poA[mt]];
            const float a1 = Xs[offlo + poB[mt]];
            const float a2 = Xs[offhi + poA[mt]];
            const float a3 = Xs[offhi + poB[mt]];
#pragma unroll
            for (int nt = 0; nt < 8; nt++)
                mma_tf32(c[mt][nt], a0, a1, a2, a3, bq[nt][0], bq[nt][1]);
        }
    }

    __syncthreads();   // all smem reads done before cb overwrite (aliases Xs/Bs)

    // ---- epilogue: bias + relu into cb[pos][66], then 2x2 maxpool ----
    float* cb = sm;    // [576][66] = 38016 floats < 42656
#pragma unroll
    for (int mt = 0; mt < 4; mt++) {
        const int row = (wid * 4 + mt) * 16 + grp;
#pragma unroll
        for (int nt = 0; nt < 8; nt++) {
            const int col = nt * 8 + qid * 2;
            const float b0 = s_b[col], b1 = s_b[col + 1];
            cb[row * 66 + col]           = fmaxf(c[mt][nt][0] + b0, 0.0f);
            cb[row * 66 + col + 1]       = fmaxf(c[mt][nt][1] + b1, 0.0f);
            cb[(row + 8) * 66 + col]     = fmaxf(c[mt][nt][2] + b0, 0.0f);
            cb[(row + 8) * 66 + col + 1] = fmaxf(c[mt][nt][3] + b1, 0.0f);
        }
    }
    __syncthreads();

    float* outb = g_p2 + bb * 9216;
    for (int i = tid; i < 9216; i += 288) {
        const int oc = i / 144, r = i - oc * 144;
        const int py = r / 12, px = r - py * 12;
        const int p0 = (2 * py) * 24 + 2 * px;     // conv pos index (24x24)
        const float v0 = cb[p0 * 66 + oc];
        const float v1 = cb[(p0 + 1) * 66 + oc];
        const float v2 = cb[(p0 + 24) * 66 + oc];
        const float v3 = cb[(p0 + 25) * 66 + oc];
        outb[i] = fmaxf(fmaxf(v0, v1), fmaxf(v2, v3));
    }
}

// ---------------------------------------------------------------------------
// Kernel 3: fc1 GEMM, split-K (fp32)
// ---------------------------------------------------------------------------
__global__ void __launch_bounds__(256) k_fc1(const float* __restrict__ W)
{
    __shared__ float As[64][17];
    __shared__ float Bs[128][17];

    const int mb = blockIdx.x;
    const int sp = blockIdx.y;
    const int tid = threadIdx.x;
    const float* Ab = g_p2 + (mb * 64) * 9216;
    const int k0 = sp * 576;

    float acc[4][8];
#pragma unroll
    for (int i = 0; i < 4; i++)
#pragma unroll
        for (int j = 0; j < 8; j++) acc[i][j] = 0.0f;

    const int tm = tid >> 4, tn = tid & 15;
    const int lr = tid >> 2;
    const int lc = (tid & 3) * 4;

    for (int ks = 0; ks < 576; ks += 16) {
        {
            const float4 v = *(const float4*)(Ab + lr * 9216 + k0 + ks + lc);
            As[lr][lc + 0] = v.x; As[lr][lc + 1] = v.y;
            As[lr][lc + 2] = v.z; As[lr][lc + 3] = v.w;
#pragma unroll
            for (int g = 0; g < 2; g++) {
                const int rr = lr + 64 * g;
                const float4 u = *(const float4*)(W + rr * 9216 + k0 + ks + lc);
                Bs[rr][lc + 0] = u.x; Bs[rr][lc + 1] = u.y;
                Bs[rr][lc + 2] = u.z; Bs[rr][lc + 3] = u.w;
            }
        }
        __syncthreads();
#pragma unroll
        for (int kk = 0; kk < 16; kk++) {
            float a[4], bv[8];
#pragma unroll
            for (int i = 0; i < 4; i++) a[i] = As[tm * 4 + i][kk];
#pragma unroll
            for (int j = 0; j < 8; j++) bv[j] = Bs[tn * 8 + j][kk];
#pragma unroll
            for (int i = 0; i < 4; i++)
#pragma unroll
                for (int j = 0; j < 8; j++)
                    acc[i][j] = fmaf(a[i], bv[j], acc[i][j]);
        }
        __syncthreads();
    }

    float* out = g_part + sp * (512 * 128) + (mb * 64) * 128;
#pragma unroll
    for (int i = 0; i < 4; i++)
#pragma unroll
        for (int j = 0; j < 8; j++)
            out[(tm * 4 + i) * 128 + tn * 8 + j] = acc[i][j];
}

// ---------------------------------------------------------------------------
// Kernel 4: reduce split-K partials + bias + ReLU
// ---------------------------------------------------------------------------
__global__ void k_fc1red(const float* __restrict__ b1)
{
    const int idx = blockIdx.x * blockDim.x + threadIdx.x;
    const int n = idx & 127;
    float s = b1[n];
#pragma unroll
    for (int sp = 0; sp < 16; sp++) s += g_part[sp * 65536 + idx];
    g_h[idx] = fmaxf(s, 0.0f);
}

// ---------------------------------------------------------------------------
// Kernel 5: fc2 (128 -> 10)
// ---------------------------------------------------------------------------
__global__ void __launch_bounds__(128) k_fc2(const float* __restrict__ W2,
                                             const float* __restrict__ b2,
                                             float* __restrict__ out)
{
    __shared__ float sh[128];
    const int bb = blockIdx.x;
    const int tid = threadIdx.x;
    sh[tid] = g_h[bb * 128 + tid];
    __syncthreads();
    const int warp = tid >> 5, lane = tid & 31;
    for (int o = warp; o < 10; o += 4) {
        float s = 0.0f;
#pragma unroll
        for (int i = 0; i < 4; i++)
            s = fmaf(sh[lane + 32 * i], W2[o * 128 + lane + 32 * i], s);
#pragma unroll
        for (int off = 16; off > 0; off >>= 1)
            s += __shfl_down_sync(0xffffffffu, s, off);
        if (lane == 0) out[bb * 10 + o] = s + b2[o];
    }
}

// ---------------------------------------------------------------------------
extern "C" void kernel_launch(void* const* d_in, const int* in_sizes, int n_in,
                              void* d_out, int out_size)
{
    const float* x   = (const float*)d_in[0];
    const float* c1w = (const float*)d_in[1];
    const float* c1b = (const float*)d_in[2];
    const float* c2w = (const float*)d_in[3];
    const float* c2b = (const float*)d_in[4];
    const float* f1w = (const float*)d_in[5];
    const float* f1b = (const float*)d_in[6];
    const float* f2w = (const float*)d_in[7];
    const float* f2b = (const float*)d_in[8];
    float* out = (float*)d_out;

    cudaFuncSetAttribute(k_conv2, cudaFuncAttributeMaxDynamicSharedMemorySize,
                         C2_DSMEM);

    k_conv1<<<512, 256>>>(x, c1w, c1b);
    k_conv2<<<512, 288, C2_DSMEM>>>(c2w, c2b);
    dim3 g3(8, 16);
    k_fc1<<<g3, 256>>>(f1w);
    k_fc1red<<<256, 256>>>(f1b);
    k_fc2<<<512, 128>>>(f2w, f2b, out);
}